// round 3
// baseline (speedup 1.0000x reference)
#include <cuda_runtime.h>

// ---------------------------------------------------------------------------
// KoopmanNet: encoder MLP (128->256->256->5) over B*T rows,
//             16-step latent scan with tiny omega-MLPs,
//             decoder MLP (5->256->256->128) over 17*B latents.
// Output layout (float32): y_preds [17][16384][128] then g_list [17][16384][5].
// ---------------------------------------------------------------------------

#define BQ   16384
#define TT   17
#define NN   128
#define HH   256
#define DD   5
#define SSTEPS 16
#define HOX  32
#define DTC  0.01f

static const int ROWS     = BQ * TT;        // 278528
static const int TM       = 64;             // rows per block
static const int NTILES   = ROWS / TM;      // 4352 (exact)
static const long YP_ELEMS = (long)TT * BQ * NN; // 35651584

#define HSTR 260   // padded stride for 256-wide hidden tiles in smem

// scratch for latents [s][b][d]
__device__ float g_latents[TT * BQ * DD];

__device__ __forceinline__ float reluf(float v) { return v > 0.f ? v : 0.f; }
__device__ __forceinline__ float clip5(float v) { return fminf(fmaxf(v, -5.f), 5.f); }

// ---------------------------------------------------------------------------
// Encoder: rows m = b*17 + t of x -> g[b][t][:5], written as g_list[t][b][d]
// ---------------------------------------------------------------------------
__global__ __launch_bounds__(256, 1)
void enc_kernel(const float* __restrict__ x,
                const float* __restrict__ W1, const float* __restrict__ b1,
                const float* __restrict__ W2, const float* __restrict__ b2,
                const float* __restrict__ W3, const float* __restrict__ b3,
                float* __restrict__ gl)
{
    extern __shared__ float sm[];
    float* xs  = sm;                   // 64*128
    float* h1s = sm + TM * NN;         // 64*HSTR
    float* h2s = h1s + TM * HSTR;      // 64*HSTR

    const int tid = threadIdx.x;
    const int tr  = tid >> 4;          // 0..15
    const int tc  = tid & 15;          // 0..15
    const int rbase = blockIdx.x * TM;

    // ---- load x tile (64x128) ----
    {
        const float4* xg = reinterpret_cast<const float4*>(x) + (size_t)rbase * (NN / 4);
        float4* xs4 = reinterpret_cast<float4*>(xs);
#pragma unroll
        for (int i = 0; i < (TM * NN / 4) / 256; i++)
            xs4[i * 256 + tid] = xg[i * 256 + tid];
    }
    __syncthreads();

    float acc[4][16];

    // ---- layer 1: (64x128) @ (128x256) ----
#pragma unroll
    for (int i = 0; i < 4; i++)
#pragma unroll
        for (int j = 0; j < 16; j++) acc[i][j] = 0.f;

#pragma unroll 2
    for (int k = 0; k < NN; k++) {
        float a0 = xs[(tr * 4 + 0) * NN + k];
        float a1 = xs[(tr * 4 + 1) * NN + k];
        float a2 = xs[(tr * 4 + 2) * NN + k];
        float a3 = xs[(tr * 4 + 3) * NN + k];
        const float4* w = reinterpret_cast<const float4*>(W1 + k * HH + tc * 16);
        float4 w0 = w[0], w1 = w[1], w2 = w[2], w3 = w[3];
        float bb[16] = {w0.x, w0.y, w0.z, w0.w, w1.x, w1.y, w1.z, w1.w,
                        w2.x, w2.y, w2.z, w2.w, w3.x, w3.y, w3.z, w3.w};
#pragma unroll
        for (int j = 0; j < 16; j++) {
            float bv = bb[j];
            acc[0][j] += a0 * bv;
            acc[1][j] += a1 * bv;
            acc[2][j] += a2 * bv;
            acc[3][j] += a3 * bv;
        }
    }
#pragma unroll
    for (int j = 0; j < 16; j++) {
        float bias = b1[tc * 16 + j];
#pragma unroll
        for (int i = 0; i < 4; i++)
            h1s[(tr * 4 + i) * HSTR + tc * 16 + j] = reluf(acc[i][j] + bias);
    }
    __syncthreads();

    // ---- layer 2: (64x256) @ (256x256) ----
#pragma unroll
    for (int i = 0; i < 4; i++)
#pragma unroll
        for (int j = 0; j < 16; j++) acc[i][j] = 0.f;

#pragma unroll 2
    for (int k = 0; k < HH; k++) {
        float a0 = h1s[(tr * 4 + 0) * HSTR + k];
        float a1 = h1s[(tr * 4 + 1) * HSTR + k];
        float a2 = h1s[(tr * 4 + 2) * HSTR + k];
        float a3 = h1s[(tr * 4 + 3) * HSTR + k];
        const float4* w = reinterpret_cast<const float4*>(W2 + k * HH + tc * 16);
        float4 w0 = w[0], w1 = w[1], w2 = w[2], w3 = w[3];
        float bb[16] = {w0.x, w0.y, w0.z, w0.w, w1.x, w1.y, w1.z, w1.w,
                        w2.x, w2.y, w2.z, w2.w, w3.x, w3.y, w3.z, w3.w};
#pragma unroll
        for (int j = 0; j < 16; j++) {
            float bv = bb[j];
            acc[0][j] += a0 * bv;
            acc[1][j] += a1 * bv;
            acc[2][j] += a2 * bv;
            acc[3][j] += a3 * bv;
        }
    }
#pragma unroll
    for (int j = 0; j < 16; j++) {
        float bias = b2[tc * 16 + j];
#pragma unroll
        for (int i = 0; i < 4; i++)
            h2s[(tr * 4 + i) * HSTR + tc * 16 + j] = reluf(acc[i][j] + bias);
    }
    __syncthreads();

    // ---- layer 3: (64x256) @ (256x5), strided over 320 (row,o) pairs ----
    for (int idx = tid; idx < TM * DD; idx += 256) {
        int row = idx / DD;
        int o   = idx - row * DD;
        float s = b3[o];
        const float* h2r = h2s + row * HSTR;
#pragma unroll 4
        for (int k = 0; k < HH; k++)
            s += h2r[k] * W3[k * DD + o];
        int m = rbase + row;           // m = b*17 + t
        int bb_ = m / TT;
        int t_  = m - bb_ * TT;
        gl[(long)t_ * BQ * DD + (long)bb_ * DD + o] = s;
    }
}

// ---------------------------------------------------------------------------
// Scan: one thread per batch element, 16 steps of omega-MLPs.
// ---------------------------------------------------------------------------
__global__ __launch_bounds__(256, 1)
void scan_kernel(const float* __restrict__ gl,
                 const float* __restrict__ ocW1, const float* __restrict__ ocb1,
                 const float* __restrict__ ocW2, const float* __restrict__ ocb2,
                 const float* __restrict__ ocW3, const float* __restrict__ ocb3,
                 const float* __restrict__ orW1, const float* __restrict__ orb1,
                 const float* __restrict__ orW2, const float* __restrict__ orb2,
                 const float* __restrict__ orW3, const float* __restrict__ orb3)
{
    __shared__ float s_ocW1[2 * HOX];       // 64
    __shared__ float s_ocb1[2 * HOX];       // 64
    __shared__ float s_ocW2[2 * HOX * HOX]; // 2048
    __shared__ float s_ocb2[2 * HOX];       // 64
    __shared__ float s_ocW3[2 * HOX * 2];   // 128
    __shared__ float s_ocb3[4];
    __shared__ float s_orW1[HOX];
    __shared__ float s_orb1[HOX];
    __shared__ float s_orW2[HOX * HOX];     // 1024
    __shared__ float s_orb2[HOX];
    __shared__ float s_orW3[HOX];
    __shared__ float s_orb3[1];

    const int tid = threadIdx.x;
    for (int i = tid; i < 2 * HOX; i += 256) { s_ocW1[i] = ocW1[i]; s_ocb1[i] = ocb1[i]; s_ocb2[i] = ocb2[i]; }
    for (int i = tid; i < 2 * HOX * HOX; i += 256) s_ocW2[i] = ocW2[i];
    for (int i = tid; i < 2 * HOX * 2; i += 256) s_ocW3[i] = ocW3[i];
    for (int i = tid; i < 4; i += 256) s_ocb3[i] = ocb3[i];
    for (int i = tid; i < HOX; i += 256) {
        s_orW1[i] = orW1[i]; s_orb1[i] = orb1[i]; s_orb2[i] = orb2[i]; s_orW3[i] = orW3[i];
    }
    for (int i = tid; i < HOX * HOX; i += 256) s_orW2[i] = orW2[i];
    if (tid == 0) s_orb3[0] = orb3[0];
    __syncthreads();

    const int b = blockIdx.x * 256 + tid;

    float y[5];
#pragma unroll
    for (int d = 0; d < 5; d++) y[d] = gl[(long)b * DD + d];   // g_list[0][b][d]
#pragma unroll
    for (int d = 0; d < 5; d++) g_latents[(long)b * DD + d] = y[d];

    for (int st = 1; st <= SSTEPS; st++) {
        float ynew[5];

        // --- the two complex pairs ---
#pragma unroll
        for (int kp = 0; kp < 2; kp++) {
            float yr = y[2 * kp], yi = y[2 * kp + 1];
            float r = yr * yr + yi * yi;

            float h1v[HOX];
#pragma unroll
            for (int o = 0; o < HOX; o++)
                h1v[o] = reluf(r * s_ocW1[kp * HOX + o] + s_ocb1[kp * HOX + o]);
            float h2v[HOX];
#pragma unroll 4
            for (int o = 0; o < HOX; o++) {
                float t = s_ocb2[kp * HOX + o];
#pragma unroll
                for (int i = 0; i < HOX; i++)
                    t += h1v[i] * s_ocW2[(kp * HOX + i) * HOX + o];
                h2v[o] = reluf(t);
            }
            float o0 = s_ocb3[kp * 2 + 0], o1 = s_ocb3[kp * 2 + 1];
#pragma unroll
            for (int i = 0; i < HOX; i++) {
                o0 += h2v[i] * s_ocW3[(kp * HOX + i) * 2 + 0];
                o1 += h2v[i] * s_ocW3[(kp * HOX + i) * 2 + 1];
            }
            float sc  = expf(clip5(o1) * DTC);
            float ang = o0 * DTC;
            float c = sc * cosf(ang);
            float s = sc * sinf(ang);
            ynew[2 * kp]     = yr * c - yi * s;
            ynew[2 * kp + 1] = yr * s + yi * c;
        }

        // --- the real mode ---
        {
            float v = y[4];
            float h1v[HOX];
#pragma unroll
            for (int o = 0; o < HOX; o++)
                h1v[o] = reluf(v * s_orW1[o] + s_orb1[o]);
            float h2v[HOX];
#pragma unroll 4
            for (int o = 0; o < HOX; o++) {
                float t = s_orb2[o];
#pragma unroll
                for (int i = 0; i < HOX; i++)
                    t += h1v[i] * s_orW2[i * HOX + o];
                h2v[o] = reluf(t);
            }
            float oo = s_orb3[0];
#pragma unroll
            for (int i = 0; i < HOX; i++)
                oo += h2v[i] * s_orW3[i];
            float rs = expf(clip5(oo) * DTC);
            ynew[4] = rs * v;
        }

#pragma unroll
        for (int d = 0; d < 5; d++) y[d] = ynew[d];
#pragma unroll
        for (int d = 0; d < 5; d++)
            g_latents[((long)st * BQ + b) * DD + d] = y[d];
    }
}

// ---------------------------------------------------------------------------
// Decoder: latents [s][b][5] -> y_preds [s][b][128]
// ---------------------------------------------------------------------------
#define LSTR 8

__global__ __launch_bounds__(256, 1)
void dec_kernel(const float* __restrict__ W1, const float* __restrict__ b1,
                const float* __restrict__ W2, const float* __restrict__ b2,
                const float* __restrict__ W3, const float* __restrict__ b3,
                float* __restrict__ yp)
{
    extern __shared__ float sm[];
    float* ls  = sm;                   // 64*LSTR
    float* h1s = sm + TM * LSTR;       // 64*HSTR
    float* h2s = h1s + TM * HSTR;      // 64*HSTR

    const int tid = threadIdx.x;
    const int tr  = tid >> 4;
    const int tc  = tid & 15;
    const int rbase = blockIdx.x * TM;

    // ---- load latent tile (64x5), strided over all 320 elements ----
    for (int idx = tid; idx < TM * DD; idx += 256) {
        int row = idx / DD;
        int d   = idx - row * DD;
        ls[row * LSTR + d] = g_latents[(long)(rbase + row) * DD + d];
    }
    __syncthreads();

    float acc[4][16];

    // ---- layer 1: (64x5) @ (5x256) ----
#pragma unroll
    for (int i = 0; i < 4; i++)
#pragma unroll
        for (int j = 0; j < 16; j++) acc[i][j] = 0.f;

#pragma unroll
    for (int k = 0; k < DD; k++) {
        float a0 = ls[(tr * 4 + 0) * LSTR + k];
        float a1 = ls[(tr * 4 + 1) * LSTR + k];
        float a2 = ls[(tr * 4 + 2) * LSTR + k];
        float a3 = ls[(tr * 4 + 3) * LSTR + k];
        const float4* w = reinterpret_cast<const float4*>(W1 + k * HH + tc * 16);
        float4 w0 = w[0], w1 = w[1], w2 = w[2], w3 = w[3];
        float bb[16] = {w0.x, w0.y, w0.z, w0.w, w1.x, w1.y, w1.z, w1.w,
                        w2.x, w2.y, w2.z, w2.w, w3.x, w3.y, w3.z, w3.w};
#pragma unroll
        for (int j = 0; j < 16; j++) {
            float bv = bb[j];
            acc[0][j] += a0 * bv;
            acc[1][j] += a1 * bv;
            acc[2][j] += a2 * bv;
            acc[3][j] += a3 * bv;
        }
    }
#pragma unroll
    for (int j = 0; j < 16; j++) {
        float bias = b1[tc * 16 + j];
#pragma unroll
        for (int i = 0; i < 4; i++)
            h1s[(tr * 4 + i) * HSTR + tc * 16 + j] = reluf(acc[i][j] + bias);
    }
    __syncthreads();

    // ---- layer 2: (64x256) @ (256x256) ----
#pragma unroll
    for (int i = 0; i < 4; i++)
#pragma unroll
        for (int j = 0; j < 16; j++) acc[i][j] = 0.f;

#pragma unroll 2
    for (int k = 0; k < HH; k++) {
        float a0 = h1s[(tr * 4 + 0) * HSTR + k];
        float a1 = h1s[(tr * 4 + 1) * HSTR + k];
        float a2 = h1s[(tr * 4 + 2) * HSTR + k];
        float a3 = h1s[(tr * 4 + 3) * HSTR + k];
        const float4* w = reinterpret_cast<const float4*>(W2 + k * HH + tc * 16);
        float4 w0 = w[0], w1 = w[1], w2 = w[2], w3 = w[3];
        float bb[16] = {w0.x, w0.y, w0.z, w0.w, w1.x, w1.y, w1.z, w1.w,
                        w2.x, w2.y, w2.z, w2.w, w3.x, w3.y, w3.z, w3.w};
#pragma unroll
        for (int j = 0; j < 16; j++) {
            float bv = bb[j];
            acc[0][j] += a0 * bv;
            acc[1][j] += a1 * bv;
            acc[2][j] += a2 * bv;
            acc[3][j] += a3 * bv;
        }
    }
#pragma unroll
    for (int j = 0; j < 16; j++) {
        float bias = b2[tc * 16 + j];
#pragma unroll
        for (int i = 0; i < 4; i++)
            h2s[(tr * 4 + i) * HSTR + tc * 16 + j] = reluf(acc[i][j] + bias);
    }
    __syncthreads();

    // ---- layer 3: (64x256) @ (256x128), thread tile 4 rows x 8 cols ----
    float acc3[4][8];
#pragma unroll
    for (int i = 0; i < 4; i++)
#pragma unroll
        for (int j = 0; j < 8; j++) acc3[i][j] = 0.f;

#pragma unroll 2
    for (int k = 0; k < HH; k++) {
        float a0 = h2s[(tr * 4 + 0) * HSTR + k];
        float a1 = h2s[(tr * 4 + 1) * HSTR + k];
        float a2 = h2s[(tr * 4 + 2) * HSTR + k];
        float a3 = h2s[(tr * 4 + 3) * HSTR + k];
        const float4* w = reinterpret_cast<const float4*>(W3 + k * NN + tc * 8);
        float4 w0 = w[0], w1 = w[1];
        float bb[8] = {w0.x, w0.y, w0.z, w0.w, w1.x, w1.y, w1.z, w1.w};
#pragma unroll
        for (int j = 0; j < 8; j++) {
            float bv = bb[j];
            acc3[0][j] += a0 * bv;
            acc3[1][j] += a1 * bv;
            acc3[2][j] += a2 * bv;
            acc3[3][j] += a3 * bv;
        }
    }
    float bia[8];
#pragma unroll
    for (int j = 0; j < 8; j++) bia[j] = b3[tc * 8 + j];
#pragma unroll
    for (int i = 0; i < 4; i++) {
        long m = rbase + tr * 4 + i;        // m = s*B + b
        float4 v0, v1;
        v0.x = acc3[i][0] + bia[0]; v0.y = acc3[i][1] + bia[1];
        v0.z = acc3[i][2] + bia[2]; v0.w = acc3[i][3] + bia[3];
        v1.x = acc3[i][4] + bia[4]; v1.y = acc3[i][5] + bia[5];
        v1.z = acc3[i][6] + bia[6]; v1.w = acc3[i][7] + bia[7];
        float4* o4 = reinterpret_cast<float4*>(yp + m * NN + tc * 8);
        o4[0] = v0;
        o4[1] = v1;
    }
}

// ---------------------------------------------------------------------------
// kernel_launch
// ---------------------------------------------------------------------------
extern "C" void kernel_launch(void* const* d_in, const int* in_sizes, int n_in,
                              void* d_out, int out_size)
{
    const float* x      = (const float*)d_in[0];
    const float* eW1    = (const float*)d_in[1];
    const float* eb1    = (const float*)d_in[2];
    const float* eW2    = (const float*)d_in[3];
    const float* eb2    = (const float*)d_in[4];
    const float* eW3    = (const float*)d_in[5];
    const float* eb3    = (const float*)d_in[6];
    const float* dW1    = (const float*)d_in[7];
    const float* db1    = (const float*)d_in[8];
    const float* dW2    = (const float*)d_in[9];
    const float* db2    = (const float*)d_in[10];
    const float* dW3    = (const float*)d_in[11];
    const float* db3    = (const float*)d_in[12];
    const float* ocW1   = (const float*)d_in[13];
    const float* ocb1   = (const float*)d_in[14];
    const float* ocW2   = (const float*)d_in[15];
    const float* ocb2   = (const float*)d_in[16];
    const float* ocW3   = (const float*)d_in[17];
    const float* ocb3   = (const float*)d_in[18];
    const float* orW1   = (const float*)d_in[19];
    const float* orb1   = (const float*)d_in[20];
    const float* orW2   = (const float*)d_in[21];
    const float* orb2   = (const float*)d_in[22];
    const float* orW3   = (const float*)d_in[23];
    const float* orb3   = (const float*)d_in[24];

    float* out = (float*)d_out;
    float* yp  = out;            // y_preds [17][B][128]
    float* gl  = out + YP_ELEMS; // g_list  [17][B][5]

    const int ENC_SMEM = (TM * NN + 2 * TM * HSTR) * sizeof(float);   // 165888
    const int DEC_SMEM = (TM * LSTR + 2 * TM * HSTR) * sizeof(float); // 135168

    // Unconditional (no static state allowed). Not a stream op -> capture-safe.
    cudaFuncSetAttribute(enc_kernel, cudaFuncAttributeMaxDynamicSharedMemorySize, ENC_SMEM);
    cudaFuncSetAttribute(dec_kernel, cudaFuncAttributeMaxDynamicSharedMemorySize, DEC_SMEM);

    enc_kernel<<<NTILES, 256, ENC_SMEM>>>(x, eW1, eb1, eW2, eb2, eW3, eb3, gl);

    scan_kernel<<<BQ / 256, 256>>>(gl,
                                   ocW1, ocb1, ocW2, ocb2, ocW3, ocb3,
                                   orW1, orb1, orW2, orb2, orW3, orb3);

    dec_kernel<<<NTILES, 256, DEC_SMEM>>>(dW1, db1, dW2, db2, dW3, db3, yp);
}